// round 17
// baseline (speedup 1.0000x reference)
#include <cuda_runtime.h>

#define S_     16
#define IND    128
#define OD     64
#define ED     32
#define PN     4
#define ALPHA  0.8f

#define SN_STRIDE 144     // floats; 36 float4/row; conflict-free LDS.128
#define SE_STRIDE 48      // floats; 12 float4/row
#define SA_STRIDE 132

// dynamic smem layout (float offsets)
#define OFF_N    0                      // 2 * 64*144 = 18432
#define OFF_E    18432                  // 2 * 64*48  = 6144
#define OFF_I    24576                  // 2 * 512    = 1024
#define OFF_AGG  25600                  // 4*132 = 528
#define OFF_PART 26128                  // 2048  [kg8][p][d] (reused mat0 then mat1)
#define OFF_WAX  28176                  // 128
#define OFF_W2AN 28304                  // 128
#define OFF_AE   28432                  // 32
#define OFF_SC   28464                  // 64
#define OFF_C    28528                  // 16 (pad)
#define SMEM_FLOATS 28544               // 114,176 bytes -> 2 blocks/SM

__device__ float g_wax[IND];     // W  @ a_x
__device__ float g_w2an[IND];    // W2 @ a_n

__device__ __forceinline__ void cp16(float* s, const float4* g) {
    unsigned sa = (unsigned)__cvta_generic_to_shared(s);
    asm volatile("cp.async.cg.shared.global [%0], [%1], 16;" :: "r"(sa), "l"(g));
}
#define CP_COMMIT()  asm volatile("cp.async.commit_group;")
#define CP_WAIT(n)   asm volatile("cp.async.wait_group %0;" :: "n"(n))

__device__ __forceinline__ float dot4(float4 v, float4 w) {
    return v.x * w.x + v.y * w.y + v.z * w.z + v.w * w.w;
}
__device__ __forceinline__ void ffma2(unsigned long long& d,
                                      unsigned long long a,
                                      unsigned long long b) {
    asm("fma.rn.f32x2 %0, %1, %2, %0;" : "+l"(d) : "l"(a), "l"(b));
}
__device__ __forceinline__ unsigned long long splat2(float x) {
    unsigned long long r;
    asm("mov.b64 %0, {%1, %1};" : "=l"(r) : "f"(x));
    return r;
}
__device__ __forceinline__ unsigned long long packf2(float lo, float hi) {
    unsigned long long r;
    asm("mov.b64 %0, {%1, %2};" : "=l"(r) : "f"(lo), "f"(hi));
    return r;
}

// ---------------------------------------------------------------------------
// K0: fold projection vectors
// ---------------------------------------------------------------------------
__global__ __launch_bounds__(256) void precompute_kernel(
    const float* __restrict__ W,
    const float* __restrict__ W2,
    const float* __restrict__ a)
{
    int gw   = (blockIdx.x * blockDim.x + threadIdx.x) >> 5;
    int lane = threadIdx.x & 31;
    if (gw < 2 * IND) {
        int m = gw >> 7;
        int k = gw & (IND - 1);
        const float* Wm = m ? W2 : W;
        const float* av = m ? (a + OD) : a;
        float s = Wm[k * OD + lane] * av[lane]
                + Wm[k * OD + lane + 32] * av[lane + 32];
#pragma unroll
        for (int o = 16; o; o >>= 1) s += __shfl_down_sync(0xffffffffu, s, o);
        if (lane == 0) (m ? g_w2an : g_wax)[k] = s;
    }
}

// ---------------------------------------------------------------------------
// K1: fused persistent kernel; cp.async DB; f32x2 proj; balanced phases
// ---------------------------------------------------------------------------
__global__ __launch_bounds__(256, 2) void fused_kernel(
    const float* __restrict__ input,
    const float* __restrict__ neigh,
    const float* __restrict__ ee,
    const float* __restrict__ W,
    const float* __restrict__ W2,
    const float* __restrict__ a,
    float* __restrict__ out,
    int N, int ntiles)
{
    extern __shared__ float sm[];
    float* sAgg   = sm + OFF_AGG;
    float* sPart  = sm + OFF_PART;
    float* sWax   = sm + OFF_WAX;
    float* sW2an  = sm + OFF_W2AN;
    float* sAe    = sm + OFF_AE;
    float* sScore = sm + OFF_SC;
    float* sC     = sm + OFF_C;

    const int tid  = threadIdx.x;
    const int dp   = tid & 31;     // d-pair: d = 2dp, 2dp+1
    const int kg8  = tid >> 5;     // k-group: k = kg8*16 .. +15
    const int wid  = tid >> 5;
    const int lane = tid & 31;

    unsigned long long wp[16], w2p[16];
#pragma unroll
    for (int i = 0; i < 16; ++i) {
        const float* w1 = &W [(kg8 * 16 + i) * OD + 2 * dp];
        const float* w2 = &W2[(kg8 * 16 + i) * OD + 2 * dp];
        wp[i]  = packf2(w1[0], w1[1]);
        w2p[i] = packf2(w2[0], w2[1]);
    }
    if (tid < IND) { sWax[tid] = g_wax[tid]; sW2an[tid] = g_w2an[tid]; }
    if (tid < ED)  sAe[tid] = a[2 * OD + tid];

    auto stage = [&](int tile, int buf) {
        const int n0 = tile * PN;
        float* bN = sm + OFF_N + buf * (PN * S_ * SN_STRIDE);
        float* bE = sm + OFF_E + buf * (PN * S_ * SE_STRIDE);
        float* bI = sm + OFF_I + buf * (PN * IND);
        const float4* gN = (const float4*)(neigh + (size_t)n0 * S_ * IND);
#pragma unroll
        for (int it = 0; it < 8; ++it) {
            int idx = tid + 256 * it;
            int r = idx >> 5, c = idx & 31;
            cp16(bN + (r * 36 + c) * 4, gN + idx);
        }
        const float4* gE = (const float4*)(ee + (size_t)n0 * S_ * ED);
#pragma unroll
        for (int it = 0; it < 2; ++it) {
            int idx = tid + 256 * it;
            int r = idx >> 3, c = idx & 7;
            cp16(bE + (r * 12 + c) * 4, gE + idx);
        }
        if (tid < 128)
            cp16(bI + tid * 4, (const float4*)(input + (size_t)n0 * IND) + tid);
    };

    int buf = 0;
    stage(blockIdx.x, 0);
    CP_COMMIT();

    for (int tile = blockIdx.x; tile < ntiles; tile += gridDim.x) {
        const int n0  = tile * PN;
        const int nxt = tile + gridDim.x;

        if (nxt < ntiles) {
            stage(nxt, buf ^ 1);
            CP_COMMIT();
            CP_WAIT(1);
        } else {
            CP_WAIT(0);
        }
        __syncthreads();   // T1

        float* bN = sm + OFF_N + buf * (PN * S_ * SN_STRIDE);
        float* bE = sm + OFF_E + buf * (PN * S_ * SE_STRIDE);
        float* bI = sm + OFF_I + buf * (PN * IND);

        // c[p] = input_row . (W a_x) — one warp per node
        if (tid < PN * 32) {
            int p = tid >> 5, l = tid & 31;
            float c = dot4(((const float4*)(bI + p * IND))[l],
                           ((const float4*)sWax)[l]);
#pragma unroll
            for (int o = 16; o; o >>= 1) c += __shfl_down_sync(0xffffffffu, c, o);
            if (l == 0) sC[p] = c;
        }

        // raw scores: row g = p*S+s, 4 lanes each; split accumulators
        {
            int g = tid >> 2, jj = tid & 3;
            const float4* nr4 = (const float4*)(bN + g * SN_STRIDE);
            const float4* w4  = (const float4*)sW2an;
            float s0 = 0.f, s1 = 0.f;
#pragma unroll
            for (int i = 0; i < 8; i += 2) {
                s0 += dot4(nr4[jj + 4 * i],       w4[jj + 4 * i]);
                s1 += dot4(nr4[jj + 4 * (i + 1)], w4[jj + 4 * (i + 1)]);
            }
            const float4* er4 = (const float4*)(bE + g * SE_STRIDE);
            const float4* a4  = (const float4*)sAe;
            s0 += dot4(er4[jj],     a4[jj]);
            s1 += dot4(er4[jj + 4], a4[jj + 4]);
            float sc = s0 + s1;
            sc += __shfl_down_sync(0xffffffffu, sc, 2, 4);
            sc += __shfl_down_sync(0xffffffffu, sc, 1, 4);
            if (jj == 0) sScore[g] = sc;
        }
        __syncthreads();   // S2

        // parallel softmax: 64 threads, one per (p,s); width-16 butterflies
        if (tid < PN * S_) {
            int p = tid >> 4;
            float v = sScore[tid] + sC[p];
            v = v > 0.f ? v : ALPHA * v;
            float mx = v;
#pragma unroll
            for (int o = 8; o; o >>= 1)
                mx = fmaxf(mx, __shfl_xor_sync(0xffffffffu, mx, o, 16));
            float e = __expf(v - mx);
            float sum = e;
#pragma unroll
            for (int o = 8; o; o >>= 1)
                sum += __shfl_xor_sync(0xffffffffu, sum, o, 16);
            sScore[tid] = e / sum;
        }
        // input @ W partials (f32x2): sPart[kg8][p][d-pair]
#pragma unroll
        for (int p = 0; p < PN; ++p) {
            const float4* xi = (const float4*)(bI + p * IND + kg8 * 16);
            unsigned long long acc = 0ull;
#pragma unroll
            for (int q = 0; q < 4; ++q) {
                float4 v = xi[q];
                ffma2(acc, wp[q * 4 + 0], splat2(v.x));
                ffma2(acc, wp[q * 4 + 1], splat2(v.y));
                ffma2(acc, wp[q * 4 + 2], splat2(v.z));
                ffma2(acc, wp[q * 4 + 3], splat2(v.w));
            }
            *(unsigned long long*)&sPart[(kg8 * PN + p) * OD + 2 * dp] = acc;
        }
        __syncthreads();   // S3

        // balanced aggregation: all 8 warps, half a node-row each
        {
            int p = wid >> 1, h = wid & 1;
            int col4 = h * 16 + (lane & 15);
            int sbase = (lane >> 4) * 8;          // s-half
            float4 acc = make_float4(0.f, 0.f, 0.f, 0.f);
#pragma unroll
            for (int i = 0; i < 8; ++i) {
                int s = sbase + i;
                float w = sScore[p * S_ + s];
                float4 v = ((const float4*)(bN + (p * S_ + s) * SN_STRIDE))[col4];
                acc.x += w * v.x; acc.y += w * v.y;
                acc.z += w * v.z; acc.w += w * v.w;
            }
            acc.x += __shfl_xor_sync(0xffffffffu, acc.x, 16);
            acc.y += __shfl_xor_sync(0xffffffffu, acc.y, 16);
            acc.z += __shfl_xor_sync(0xffffffffu, acc.z, 16);
            acc.w += __shfl_xor_sync(0xffffffffu, acc.w, 16);
            if (lane < 16)
                ((float4*)(sAgg + p * SA_STRIDE))[col4] = acc;
        }
        if (tid < 128) {
            // warps 0-3: edge aggregation
            int p = tid >> 5, e_ = tid & 31;
            const float* att = sScore + p * S_;
            float a0 = 0.f, a1 = 0.f;
#pragma unroll
            for (int s = 0; s < S_; s += 2) {
                a0 += att[s]     * bE[(p * S_ + s)     * SE_STRIDE + e_];
                a1 += att[s + 1] * bE[(p * S_ + s + 1) * SE_STRIDE + e_];
            }
            out[(size_t)(n0 + p) * 160 + 128 + e_] = a0 + a1;
        } else {
            // warps 4-7: mat0 (input@W) reduce + store
            int t = tid - 128;
            int p = t >> 5, dp2 = t & 31;
            float2 v = make_float2(0.f, 0.f);
#pragma unroll
            for (int kg = 0; kg < 8; ++kg) {
                float2 u = *(const float2*)&sPart[(kg * PN + p) * OD + 2 * dp2];
                v.x += u.x; v.y += u.y;
            }
            *(float2*)&out[(size_t)(n0 + p) * 160 + 2 * dp2] = v;
        }
        __syncthreads();   // S4 — sAgg complete; mat0 partials consumed

        // agg @ W2 partials (f32x2) into the SAME sPart region
#pragma unroll
        for (int p = 0; p < PN; ++p) {
            const float4* xa = (const float4*)(sAgg + p * SA_STRIDE + kg8 * 16);
            unsigned long long acc = 0ull;
#pragma unroll
            for (int q = 0; q < 4; ++q) {
                float4 v = xa[q];
                ffma2(acc, w2p[q * 4 + 0], splat2(v.x));
                ffma2(acc, w2p[q * 4 + 1], splat2(v.y));
                ffma2(acc, w2p[q * 4 + 2], splat2(v.z));
                ffma2(acc, w2p[q * 4 + 3], splat2(v.w));
            }
            *(unsigned long long*)&sPart[(kg8 * PN + p) * OD + 2 * dp] = acc;
        }
        __syncthreads();   // S5

        // reduce mat1 and store
        if (tid < 128) {
            int p = tid >> 5, dp2 = tid & 31;
            float2 v = make_float2(0.f, 0.f);
#pragma unroll
            for (int kg = 0; kg < 8; ++kg) {
                float2 u = *(const float2*)&sPart[(kg * PN + p) * OD + 2 * dp2];
                v.x += u.x; v.y += u.y;
            }
            *(float2*)&out[(size_t)(n0 + p) * 160 + 64 + 2 * dp2] = v;
        }

        buf ^= 1;
    }
}

// ---------------------------------------------------------------------------
extern "C" void kernel_launch(void* const* d_in, const int* in_sizes, int n_in,
                              void* d_out, int out_size) {
    const float* input = (const float*)d_in[0];
    const float* neigh = (const float*)d_in[1];
    const float* ee    = (const float*)d_in[2];
    const float* W     = (const float*)d_in[3];
    const float* W2    = (const float*)d_in[4];
    const float* a     = (const float*)d_in[5];
    float* out = (float*)d_out;

    int N = in_sizes[0] / IND;      // 50000
    int ntiles = N / PN;            // 12500

    static bool attr_set = false;
    if (!attr_set) {
        cudaFuncSetAttribute(fused_kernel,
                             cudaFuncAttributeMaxDynamicSharedMemorySize,
                             SMEM_FLOATS * (int)sizeof(float));
        attr_set = true;
    }

    precompute_kernel<<<32, 256>>>(W, W2, a);
    fused_kernel<<<296, 256, SMEM_FLOATS * sizeof(float)>>>(
        input, neigh, ee, W, W2, a, out, N, ntiles);
}